// round 2
// baseline (speedup 1.0000x reference)
#include <cuda_runtime.h>
#include <cstdint>

#define FDIM  64
#define NRBF  32
#define NC    9
#define CSTR  (FDIM * NC)   // 576 floats per atom (compressed irrep form)

#define MAXN  24000

// Scratch (no cudaMalloc allowed)
__device__ float g_Xn[MAXN * CSTR];   // normalized X, compressed
__device__ float g_Y [MAXN * CSTR];   // mixed Y (then reused for dX)
__device__ float g_Mg[MAXN * CSTR];   // message accumulator (then reused for T)

// ---------------------------------------------------------------- helpers
__device__ __forceinline__ float silu_f(float x) {
    return __fdividef(x, 1.0f + __expf(-x));
}

__device__ __forceinline__ void red_v4(float* addr, float4 v) {
    asm volatile("red.global.add.v4.f32 [%0], {%1,%2,%3,%4};"
                 :: "l"(addr), "f"(v.x), "f"(v.y), "f"(v.z), "f"(v.w)
                 : "memory");
}

// comp order: [c0, a01, a02, a12, s00, s11, s01, s02, s12]
__device__ __forceinline__ void comp2mat(const float c[9], float t[3][3]) {
    t[0][0] = c[0] + c[4];
    t[1][1] = c[0] + c[5];
    t[2][2] = c[0] - c[4] - c[5];
    t[0][1] = c[6] + c[1];  t[1][0] = c[6] - c[1];
    t[0][2] = c[7] + c[2];  t[2][0] = c[7] - c[2];
    t[1][2] = c[8] + c[3];  t[2][1] = c[8] - c[3];
}

__device__ __forceinline__ void mat2comp(const float t[3][3], float c[9]) {
    float c0 = (t[0][0] + t[1][1] + t[2][2]) * (1.0f / 3.0f);
    c[0] = c0;
    c[1] = 0.5f * (t[0][1] - t[1][0]);
    c[2] = 0.5f * (t[0][2] - t[2][0]);
    c[3] = 0.5f * (t[1][2] - t[2][1]);
    c[4] = t[0][0] - c0;
    c[5] = t[1][1] - c0;
    c[6] = 0.5f * (t[0][1] + t[1][0]);
    c[7] = 0.5f * (t[0][2] + t[2][0]);
    c[8] = 0.5f * (t[1][2] + t[2][1]);
}

// ---------------------------------------------------------------- zero scratch
__global__ void zero_kernel(float4* __restrict__ p, int n4) {
    int i = blockIdx.x * blockDim.x + threadIdx.x;
    int stride = gridDim.x * blockDim.x;
    float4 z = make_float4(0.f, 0.f, 0.f, 0.f);
    for (; i < n4; i += stride) p[i] = z;
}

// ---------------------------------------------------------------- K1: normalize + decompose
__global__ void atom_pre(const float* __restrict__ X, float* __restrict__ Xn, int N) {
    int t = blockIdx.x * blockDim.x + threadIdx.x;
    if (t >= N * FDIM) return;
    int n = t / FDIM, f = t % FDIM;
    const float* p = X + (size_t)t * 9;
    float m[9];
#pragma unroll
    for (int i = 0; i < 9; i++) m[i] = p[i];
    float tn = 0.f;
#pragma unroll
    for (int i = 0; i < 9; i++) tn += m[i] * m[i];
    float inv = 1.0f / (tn + 1.0f);
#pragma unroll
    for (int i = 0; i < 9; i++) m[i] *= inv;
    // decompose (m[i*3+j] = t_ij)
    float c0  = (m[0] + m[4] + m[8]) * (1.0f / 3.0f);
    float a01 = 0.5f * (m[1] - m[3]);
    float a02 = 0.5f * (m[2] - m[6]);
    float a12 = 0.5f * (m[5] - m[7]);
    float s00 = m[0] - c0;
    float s11 = m[4] - c0;
    float s01 = 0.5f * (m[1] + m[3]);
    float s02 = 0.5f * (m[2] + m[6]);
    float s12 = 0.5f * (m[5] + m[7]);
    float* o = Xn + (size_t)n * CSTR + f;
    o[0 * 64] = c0;  o[1 * 64] = a01; o[2 * 64] = a02; o[3 * 64] = a12;
    o[4 * 64] = s00; o[5 * 64] = s11; o[6 * 64] = s01; o[7 * 64] = s02; o[8 * 64] = s12;
}

// ---------------------------------------------------------------- K2/K5b: channel mix (9 subspace GEMMs)
// Out[n][c][g] = sum_f Wsel(c)[g][f] * In[n][c][f];  Wsel: 0 for c=0, 1 for c in 1..3, 2 for c in 4..8
#define MIX_AB    16
#define MIX_PAD   584   // CSTR + 8 (bank spread)
#define MIX_SMEM  ((3 * 4096 + MIX_AB * MIX_PAD) * 4)

__global__ void __launch_bounds__(256) mix_kernel(const float* __restrict__ In,
                                                  float* __restrict__ Out,
                                                  const float* __restrict__ W, int N) {
    extern __shared__ float sm[];
    float* WT  = sm;                 // 3 * [f][g] 64x64
    float* InS = sm + 3 * 4096;      // 16 x MIX_PAD
    int t  = threadIdx.x;
    int nb = blockIdx.x * MIX_AB;

    for (int idx = t; idx < 3 * 4096; idx += 256) {
        int mtx = idx >> 12, rem = idx & 4095;
        int g = rem >> 6, f = rem & 63;
        WT[mtx * 4096 + f * 64 + g] = W[idx];
    }
    for (int idx = t; idx < MIX_AB * CSTR; idx += 256) {
        int a = idx / CSTR, off = idx % CSTR;
        int n = nb + a;
        InS[a * MIX_PAD + off] = (n < N) ? In[(size_t)n * CSTR + off] : 0.f;
    }
    __syncthreads();

    int a = t >> 4, g0 = (t & 15) * 4;
    float acc[9][4];
#pragma unroll
    for (int c = 0; c < 9; c++)
#pragma unroll
        for (int i = 0; i < 4; i++) acc[c][i] = 0.f;

    const float* ip = InS + a * MIX_PAD;
#pragma unroll 4
    for (int f = 0; f < 64; f++) {
        float4 w0 = *(const float4*)&WT[         f * 64 + g0];
        float4 w1 = *(const float4*)&WT[4096  +  f * 64 + g0];
        float4 w2 = *(const float4*)&WT[8192  +  f * 64 + g0];
        float x;
        x = ip[0 * 64 + f];
        acc[0][0] += w0.x * x; acc[0][1] += w0.y * x; acc[0][2] += w0.z * x; acc[0][3] += w0.w * x;
#pragma unroll
        for (int c = 1; c < 4; c++) {
            x = ip[c * 64 + f];
            acc[c][0] += w1.x * x; acc[c][1] += w1.y * x; acc[c][2] += w1.z * x; acc[c][3] += w1.w * x;
        }
#pragma unroll
        for (int c = 4; c < 9; c++) {
            x = ip[c * 64 + f];
            acc[c][0] += w2.x * x; acc[c][1] += w2.y * x; acc[c][2] += w2.z * x; acc[c][3] += w2.w * x;
        }
    }
    int n = nb + a;
    if (n < N) {
#pragma unroll
        for (int c = 0; c < 9; c++) {
            float4 v = make_float4(acc[c][0], acc[c][1], acc[c][2], acc[c][3]);
            *(float4*)&Out[(size_t)n * CSTR + c * 64 + g0] = v;
        }
    }
}

// ---------------------------------------------------------------- K3: fused edge MLP + message scatter
#define TE        64
#define ETHR      512
#define A0_OFF    24576
#define A0_PITCH  68
#define A1_OFF    (A0_OFF + 32 * A0_PITCH)
#define A2_OFF    (A1_OFF + 64 * A0_PITCH)
#define CS_OFF    (A2_OFF + 128 * A0_PITCH)
#define BS_OFF    (CS_OFF + 64)
#define RPITCH    200
#define EDGE_SMEM ((BS_OFF + 384) * 4)

__global__ void __launch_bounds__(ETHR, 1) edge_kernel(
    const float* __restrict__ rfv, const float* __restrict__ dij,
    const int* __restrict__ pairs,
    const float* __restrict__ W0, const float* __restrict__ b0,
    const float* __restrict__ W1, const float* __restrict__ b1,
    const float* __restrict__ W2, const float* __restrict__ b2,
    const float* __restrict__ Y, float* __restrict__ Msg, int E)
{
    extern __shared__ float sm[];
    float* Wb = sm;            // weights (max 128*192) / later R buffer (TE x RPITCH)
    float* A0 = sm + A0_OFF;
    float* A1 = sm + A1_OFF;
    float* A2 = sm + A2_OFF;
    float* Cs = sm + CS_OFF;
    float* Bs = sm + BS_OFF;

    int t  = threadIdx.x;
    int e0 = blockIdx.x * TE;

    if (t < 384) {
        float v = (t < 64) ? b0[t] : ((t < 192) ? b1[t - 64] : b2[t - 192]);
        Bs[t] = v;
    }
    if (t < TE) {
        int ge = e0 + t;
        float d = (ge < E) ? dij[ge] : 2.0f;
        Cs[t] = (d < 1.0f) ? 0.5f * (cospif(d) + 1.0f) : 0.0f;
    }
    for (int idx = t; idx < TE * NRBF; idx += ETHR) {       // rfv -> A0[k][e]
        int e = idx >> 5, k = idx & 31;
        int ge = e0 + e;
        A0[k * A0_PITCH + e] = (ge < E) ? rfv[(size_t)ge * NRBF + k] : 0.f;
    }
    for (int idx = t; idx < 64 * 32; idx += ETHR) {         // W0T
        int j = idx >> 5, k = idx & 31;
        Wb[k * 64 + j] = W0[idx];
    }
    __syncthreads();

    int eg = t & 15;          // edge group: edges 4*eg .. 4*eg+3
    int jg = t >> 4;          // output group 0..31

    // ---- layer 1: 32 -> 64, thread tile 4e x 2j
    {
        float b_0 = Bs[2 * jg], b_1 = Bs[2 * jg + 1];
        float acc0[4], acc1[4];
#pragma unroll
        for (int i = 0; i < 4; i++) { acc0[i] = b_0; acc1[i] = b_1; }
#pragma unroll 8
        for (int k = 0; k < 32; k++) {
            float4 a4 = *(const float4*)&A0[k * A0_PITCH + 4 * eg];
            float2 w  = *(const float2*)&Wb[k * 64 + 2 * jg];
            acc0[0] += w.x * a4.x; acc0[1] += w.x * a4.y; acc0[2] += w.x * a4.z; acc0[3] += w.x * a4.w;
            acc1[0] += w.y * a4.x; acc1[1] += w.y * a4.y; acc1[2] += w.y * a4.z; acc1[3] += w.y * a4.w;
        }
#pragma unroll
        for (int i = 0; i < 4; i++) {
            A1[(2 * jg)     * A0_PITCH + 4 * eg + i] = silu_f(acc0[i]);
            A1[(2 * jg + 1) * A0_PITCH + 4 * eg + i] = silu_f(acc1[i]);
        }
    }
    __syncthreads();
    for (int idx = t; idx < 128 * 64; idx += ETHR) {        // W1T
        int j = idx >> 6, k = idx & 63;
        Wb[k * 128 + j] = W1[idx];
    }
    __syncthreads();

    // ---- layer 2: 64 -> 128, thread tile 4e x 4j
    {
        int j0 = 4 * jg;
        float acc[4][4];
#pragma unroll
        for (int jj = 0; jj < 4; jj++) {
            float b = Bs[64 + j0 + jj];
#pragma unroll
            for (int i = 0; i < 4; i++) acc[jj][i] = b;
        }
#pragma unroll 4
        for (int k = 0; k < 64; k++) {
            float4 a4 = *(const float4*)&A1[k * A0_PITCH + 4 * eg];
            float4 w  = *(const float4*)&Wb[k * 128 + j0];
            acc[0][0] += w.x * a4.x; acc[0][1] += w.x * a4.y; acc[0][2] += w.x * a4.z; acc[0][3] += w.x * a4.w;
            acc[1][0] += w.y * a4.x; acc[1][1] += w.y * a4.y; acc[1][2] += w.y * a4.z; acc[1][3] += w.y * a4.w;
            acc[2][0] += w.z * a4.x; acc[2][1] += w.z * a4.y; acc[2][2] += w.z * a4.z; acc[2][3] += w.z * a4.w;
            acc[3][0] += w.w * a4.x; acc[3][1] += w.w * a4.y; acc[3][2] += w.w * a4.z; acc[3][3] += w.w * a4.w;
        }
        __syncthreads();   // all Wb reads done before W2T overwrite; A2 writes before next read
#pragma unroll
        for (int jj = 0; jj < 4; jj++)
#pragma unroll
            for (int i = 0; i < 4; i++)
                A2[(j0 + jj) * A0_PITCH + 4 * eg + i] = silu_f(acc[jj][i]);
    }
    __syncthreads();
    for (int idx = t; idx < 192 * 128; idx += ETHR) {       // W2T
        int j = idx >> 7, k = idx & 127;
        Wb[k * 192 + j] = W2[idx];
    }
    __syncthreads();

    // ---- layer 3: 128 -> 192, thread tile 4e x 6j
    {
        int j0 = 6 * jg;
        float acc[6][4];
#pragma unroll
        for (int jj = 0; jj < 6; jj++) {
            float b = Bs[192 + j0 + jj];
#pragma unroll
            for (int i = 0; i < 4; i++) acc[jj][i] = b;
        }
#pragma unroll 4
        for (int k = 0; k < 128; k++) {
            float4 a4 = *(const float4*)&A2[k * A0_PITCH + 4 * eg];
            float2 wa = *(const float2*)&Wb[k * 192 + j0];
            float2 wb2 = *(const float2*)&Wb[k * 192 + j0 + 2];
            float2 wc = *(const float2*)&Wb[k * 192 + j0 + 4];
            acc[0][0] += wa.x * a4.x;  acc[0][1] += wa.x * a4.y;  acc[0][2] += wa.x * a4.z;  acc[0][3] += wa.x * a4.w;
            acc[1][0] += wa.y * a4.x;  acc[1][1] += wa.y * a4.y;  acc[1][2] += wa.y * a4.z;  acc[1][3] += wa.y * a4.w;
            acc[2][0] += wb2.x * a4.x; acc[2][1] += wb2.x * a4.y; acc[2][2] += wb2.x * a4.z; acc[2][3] += wb2.x * a4.w;
            acc[3][0] += wb2.y * a4.x; acc[3][1] += wb2.y * a4.y; acc[3][2] += wb2.y * a4.z; acc[3][3] += wb2.y * a4.w;
            acc[4][0] += wc.x * a4.x;  acc[4][1] += wc.x * a4.y;  acc[4][2] += wc.x * a4.z;  acc[4][3] += wc.x * a4.w;
            acc[5][0] += wc.y * a4.x;  acc[5][1] += wc.y * a4.y;  acc[5][2] += wc.y * a4.z;  acc[5][3] += wc.y * a4.w;
        }
        __syncthreads();   // Wb reads done; Wb becomes R
#pragma unroll
        for (int jj = 0; jj < 6; jj++)
#pragma unroll
            for (int i = 0; i < 4; i++) {
                int e = 4 * eg + i;
                Wb[e * RPITCH + j0 + jj] = silu_f(acc[jj][i]) * Cs[e];
            }
    }
    __syncthreads();

    // ---- scatter: msg_c = r_sel(c) * Y_c[src], atomically added into Msg[dst]
    {
        float* R = Wb;
        int warp = t >> 5, lane = t & 31;
        int sub = lane & 15;         // f-chunk (16 x float4 = 64 f)
        int half = lane >> 4;
#pragma unroll
        for (int pair = 0; pair < 2; pair++) {
            int el = warp * 4 + pair * 2 + half;
            int ge = e0 + el;
            if (ge < E) {
                int dst = pairs[ge];
                int src = pairs[E + ge];
                const float* yb = Y   + (size_t)src * CSTR;
                float*       mb = Msg + (size_t)dst * CSTR;
                int f0 = sub * 4;
#pragma unroll
                for (int c = 0; c < 9; c++) {
                    int ri = (c == 0) ? 0 : ((c < 4) ? 1 : 2);
                    float4 y4 = *(const float4*)&yb[c * 64 + f0];
                    const float* rr = &R[el * RPITCH + f0 * 3 + ri];
                    float4 m = make_float4(rr[0] * y4.x, rr[3] * y4.y, rr[6] * y4.z, rr[9] * y4.w);
                    red_v4(&mb[c * 64 + f0], m);
                }
            }
        }
    }
}

// ---------------------------------------------------------------- K5a: T = q*(M@Y + Y@M), normalize; in-place into Msg
__global__ void post_a(const float* __restrict__ Y, float* __restrict__ Msg,
                       const float* __restrict__ qraw, int N) {
    int t = blockIdx.x * blockDim.x + threadIdx.x;
    if (t >= N * FDIM) return;
    int n = t / FDIM, f = t % FDIM;
    const float* yp = Y   + (size_t)n * CSTR + f;
    float*       mp = Msg + (size_t)n * CSTR + f;
    float yc[9], mc[9];
#pragma unroll
    for (int c = 0; c < 9; c++) { yc[c] = yp[c * 64]; mc[c] = mp[c * 64]; }
    float Ym[3][3], Mm[3][3];
    comp2mat(yc, Ym);
    comp2mat(mc, Mm);
    float q = 1.0f + 0.1f * qraw[n];
    float T[3][3];
    float fr = 0.f;
#pragma unroll
    for (int i = 0; i < 3; i++)
#pragma unroll
        for (int j = 0; j < 3; j++) {
            float s = 0.f;
#pragma unroll
            for (int k = 0; k < 3; k++) s += Mm[i][k] * Ym[k][j] + Ym[i][k] * Mm[k][j];
            s *= q;
            T[i][j] = s;
            fr += s * s;
        }
    float inv = 1.0f / (fr + 1.0f);
    float tc[9];
    mat2comp(T, tc);
#pragma unroll
    for (int c = 0; c < 9; c++) mp[c * 64] = tc[c] * inv;
}

// ---------------------------------------------------------------- K5c: X' = Xn + dX + q * dX@dX
__global__ void finalize_k(const float* __restrict__ dXc, const float* __restrict__ Xnc,
                           const float* __restrict__ qraw, float* __restrict__ out, int N) {
    int t = blockIdx.x * blockDim.x + threadIdx.x;
    if (t >= N * FDIM) return;
    int n = t / FDIM, f = t % FDIM;
    const float* dp = dXc + (size_t)n * CSTR + f;
    const float* xp = Xnc + (size_t)n * CSTR + f;
    float dc[9], xc[9];
#pragma unroll
    for (int c = 0; c < 9; c++) { dc[c] = dp[c * 64]; xc[c] = xp[c * 64]; }
    float D[3][3], Xm[3][3];
    comp2mat(dc, D);
    comp2mat(xc, Xm);
    float q = 1.0f + 0.1f * qraw[n];
    float* o = out + (size_t)t * 9;
#pragma unroll
    for (int i = 0; i < 3; i++)
#pragma unroll
        for (int j = 0; j < 3; j++) {
            float p = 0.f;
#pragma unroll
            for (int k = 0; k < 3; k++) p += D[i][k] * D[k][j];
            o[i * 3 + j] = Xm[i][j] + D[i][j] + q * p;
        }
}

// ---------------------------------------------------------------- host
extern "C" void kernel_launch(void* const* d_in, const int* in_sizes, int n_in,
                              void* d_out, int out_size) {
    const float* X    = (const float*)d_in[0];
    const int*   prs  = (const int*)  d_in[1];
    const float* dij  = (const float*)d_in[2];
    const float* rfv  = (const float*)d_in[3];
    const float* q    = (const float*)d_in[4];
    const float* W0   = (const float*)d_in[5];
    const float* b0   = (const float*)d_in[6];
    const float* W1   = (const float*)d_in[7];
    const float* b1   = (const float*)d_in[8];
    const float* W2   = (const float*)d_in[9];
    const float* b2   = (const float*)d_in[10];
    const float* Wt   = (const float*)d_in[11];

    int N = in_sizes[4];          // atomic_charges length
    int E = in_sizes[2];          // d_ij length

    float *pXn, *pY, *pM;
    cudaGetSymbolAddress((void**)&pXn, g_Xn);
    cudaGetSymbolAddress((void**)&pY,  g_Y);
    cudaGetSymbolAddress((void**)&pM,  g_Mg);

    cudaFuncSetAttribute(edge_kernel, cudaFuncAttributeMaxDynamicSharedMemorySize, EDGE_SMEM);
    cudaFuncSetAttribute(mix_kernel,  cudaFuncAttributeMaxDynamicSharedMemorySize, MIX_SMEM);

    int nf_blocks = (N * FDIM + 255) / 256;

    atom_pre<<<nf_blocks, 256>>>(X, pXn, N);
    mix_kernel<<<(N + MIX_AB - 1) / MIX_AB, 256, MIX_SMEM>>>(pXn, pY, Wt, N);
    zero_kernel<<<2048, 256>>>((float4*)pM, N * (CSTR / 4));
    edge_kernel<<<(E + TE - 1) / TE, ETHR, EDGE_SMEM>>>(rfv, dij, prs,
                                                        W0, b0, W1, b1, W2, b2,
                                                        pY, pM, E);
    post_a<<<nf_blocks, 256>>>(pY, pM, q, N);
    mix_kernel<<<(N + MIX_AB - 1) / MIX_AB, 256, MIX_SMEM>>>(pM, pY, Wt + 3 * 64 * 64, N);
    finalize_k<<<nf_blocks, 256>>>(pY, pXn, q, (float*)d_out, N);
}

// round 9
// speedup vs baseline: 1.5703x; 1.5703x over previous
#include <cuda_runtime.h>
#include <cstdint>

#define FDIM  64
#define NRBF  32
#define NC    9
#define CSTR  (FDIM * NC)   // 576 floats per atom (compressed irrep form)

#define MAXN  24000

// Scratch (no cudaMalloc allowed)
__device__ float g_Xn[MAXN * CSTR];   // normalized X, compressed
__device__ float g_Y [MAXN * CSTR];   // mixed Y (then reused for dX)
__device__ float g_Mg[MAXN * CSTR];   // message accumulator (then reused for T)

// ---------------------------------------------------------------- helpers
__device__ __forceinline__ float silu_f(float x) {
    return __fdividef(x, 1.0f + __expf(-x));
}

__device__ __forceinline__ void red_v4(float* addr, float4 v) {
    asm volatile("red.global.add.v4.f32 [%0], {%1,%2,%3,%4};"
                 :: "l"(addr), "f"(v.x), "f"(v.y), "f"(v.z), "f"(v.w)
                 : "memory");
}

// comp order: [c0, a01, a02, a12, s00, s11, s01, s02, s12]
__device__ __forceinline__ void comp2mat(const float c[9], float t[3][3]) {
    t[0][0] = c[0] + c[4];
    t[1][1] = c[0] + c[5];
    t[2][2] = c[0] - c[4] - c[5];
    t[0][1] = c[6] + c[1];  t[1][0] = c[6] - c[1];
    t[0][2] = c[7] + c[2];  t[2][0] = c[7] - c[2];
    t[1][2] = c[8] + c[3];  t[2][1] = c[8] - c[3];
}

__device__ __forceinline__ void mat2comp(const float t[3][3], float c[9]) {
    float c0 = (t[0][0] + t[1][1] + t[2][2]) * (1.0f / 3.0f);
    c[0] = c0;
    c[1] = 0.5f * (t[0][1] - t[1][0]);
    c[2] = 0.5f * (t[0][2] - t[2][0]);
    c[3] = 0.5f * (t[1][2] - t[2][1]);
    c[4] = t[0][0] - c0;
    c[5] = t[1][1] - c0;
    c[6] = 0.5f * (t[0][1] + t[1][0]);
    c[7] = 0.5f * (t[0][2] + t[2][0]);
    c[8] = 0.5f * (t[1][2] + t[2][1]);
}

// ---------------------------------------------------------------- zero scratch
__global__ void zero_kernel(float4* __restrict__ p, int n4) {
    int i = blockIdx.x * blockDim.x + threadIdx.x;
    int stride = gridDim.x * blockDim.x;
    float4 z = make_float4(0.f, 0.f, 0.f, 0.f);
    for (; i < n4; i += stride) p[i] = z;
}

// ---------------------------------------------------------------- K1: normalize + decompose
__global__ void atom_pre(const float* __restrict__ X, float* __restrict__ Xn, int N) {
    int t = blockIdx.x * blockDim.x + threadIdx.x;
    if (t >= N * FDIM) return;
    int n = t / FDIM, f = t % FDIM;
    const float* p = X + (size_t)t * 9;
    float m[9];
#pragma unroll
    for (int i = 0; i < 9; i++) m[i] = p[i];
    float tn = 0.f;
#pragma unroll
    for (int i = 0; i < 9; i++) tn += m[i] * m[i];
    float inv = 1.0f / (tn + 1.0f);
#pragma unroll
    for (int i = 0; i < 9; i++) m[i] *= inv;
    float c0  = (m[0] + m[4] + m[8]) * (1.0f / 3.0f);
    float a01 = 0.5f * (m[1] - m[3]);
    float a02 = 0.5f * (m[2] - m[6]);
    float a12 = 0.5f * (m[5] - m[7]);
    float s00 = m[0] - c0;
    float s11 = m[4] - c0;
    float s01 = 0.5f * (m[1] + m[3]);
    float s02 = 0.5f * (m[2] + m[6]);
    float s12 = 0.5f * (m[5] + m[7]);
    float* o = Xn + (size_t)n * CSTR + f;
    o[0 * 64] = c0;  o[1 * 64] = a01; o[2 * 64] = a02; o[3 * 64] = a12;
    o[4 * 64] = s00; o[5 * 64] = s11; o[6 * 64] = s01; o[7 * 64] = s02; o[8 * 64] = s12;
}

// ---------------------------------------------------------------- K2/K5b: channel mix (9 subspace GEMMs)
#define MIX_AB    16
#define MIX_PAD   584
#define MIX_SMEM  ((3 * 4096 + MIX_AB * MIX_PAD) * 4)

__global__ void __launch_bounds__(256) mix_kernel(const float* __restrict__ In,
                                                  float* __restrict__ Out,
                                                  const float* __restrict__ W, int N) {
    extern __shared__ float sm[];
    float* WT  = sm;                 // 3 * [f][g] 64x64
    float* InS = sm + 3 * 4096;      // 16 x MIX_PAD
    int t  = threadIdx.x;
    int nb = blockIdx.x * MIX_AB;

    for (int idx = t; idx < 3 * 4096; idx += 256) {
        int mtx = idx >> 12, rem = idx & 4095;
        int g = rem >> 6, f = rem & 63;
        WT[mtx * 4096 + f * 64 + g] = W[idx];
    }
    for (int idx = t; idx < MIX_AB * CSTR; idx += 256) {
        int a = idx / CSTR, off = idx % CSTR;
        int n = nb + a;
        InS[a * MIX_PAD + off] = (n < N) ? In[(size_t)n * CSTR + off] : 0.f;
    }
    __syncthreads();

    int a = t >> 4, g0 = (t & 15) * 4;
    float acc[9][4];
#pragma unroll
    for (int c = 0; c < 9; c++)
#pragma unroll
        for (int i = 0; i < 4; i++) acc[c][i] = 0.f;

    const float* ip = InS + a * MIX_PAD;
#pragma unroll 4
    for (int f = 0; f < 64; f++) {
        float4 w0 = *(const float4*)&WT[         f * 64 + g0];
        float4 w1 = *(const float4*)&WT[4096  +  f * 64 + g0];
        float4 w2 = *(const float4*)&WT[8192  +  f * 64 + g0];
        float x;
        x = ip[0 * 64 + f];
        acc[0][0] += w0.x * x; acc[0][1] += w0.y * x; acc[0][2] += w0.z * x; acc[0][3] += w0.w * x;
#pragma unroll
        for (int c = 1; c < 4; c++) {
            x = ip[c * 64 + f];
            acc[c][0] += w1.x * x; acc[c][1] += w1.y * x; acc[c][2] += w1.z * x; acc[c][3] += w1.w * x;
        }
#pragma unroll
        for (int c = 4; c < 9; c++) {
            x = ip[c * 64 + f];
            acc[c][0] += w2.x * x; acc[c][1] += w2.y * x; acc[c][2] += w2.z * x; acc[c][3] += w2.w * x;
        }
    }
    int n = nb + a;
    if (n < N) {
#pragma unroll
        for (int c = 0; c < 9; c++) {
            float4 v = make_float4(acc[c][0], acc[c][1], acc[c][2], acc[c][3]);
            *(float4*)&Out[(size_t)n * CSTR + c * 64 + g0] = v;
        }
    }
}

// ---------------------------------------------------------------- K3: fused edge MLP + message scatter
// smem layout (floats):
//   [0, 12288)        Wb  : W0T (k*64+j, 2048) + W1T at 2048 (k*128+j, 8192); later W2T halves (k*96+jl)
//   [12288, 27520)    A0/A1/A2 activations (pitch 68); later overlaid by R (64 x 200 = 12800)
//   [27520, 27584)    Cs (cutoff per edge)
//   [27584, 27968)    Bs (biases 64+128+192)
#define TE        64
#define ETHR      512
#define WB1_OFF   2048
#define A0_OFF    12288
#define A0_PITCH  68
#define A1_OFF    (A0_OFF + 32 * A0_PITCH)
#define A2_OFF    (A1_OFF + 64 * A0_PITCH)
#define R_OFF     A0_OFF
#define CS_OFF    27520
#define BS_OFF    27584
#define RPITCH    200
#define EDGE_SMEM (27968 * 4)   // 111872 B -> 2 CTAs/SM

__global__ void __launch_bounds__(ETHR, 2) edge_kernel(
    const float* __restrict__ rfv, const float* __restrict__ dij,
    const int* __restrict__ pairs,
    const float* __restrict__ W0, const float* __restrict__ b0,
    const float* __restrict__ W1, const float* __restrict__ b1,
    const float* __restrict__ W2, const float* __restrict__ b2,
    const float* __restrict__ Y, float* __restrict__ Msg, int E)
{
    extern __shared__ float sm[];
    float* Wb = sm;
    float* A0 = sm + A0_OFF;
    float* A1 = sm + A1_OFF;
    float* A2 = sm + A2_OFF;
    float* Cs = sm + CS_OFF;
    float* Bs = sm + BS_OFF;

    int t  = threadIdx.x;
    int e0 = blockIdx.x * TE;

    if (t < 384) {
        float v = (t < 64) ? b0[t] : ((t < 192) ? b1[t - 64] : b2[t - 192]);
        Bs[t] = v;
    }
    if (t < TE) {
        int ge = e0 + t;
        float d = (ge < E) ? dij[ge] : 2.0f;
        Cs[t] = (d < 1.0f) ? 0.5f * (cospif(d) + 1.0f) : 0.0f;
    }
    for (int idx = t; idx < TE * NRBF; idx += ETHR) {       // rfv -> A0[k][e]
        int e = idx >> 5, k = idx & 31;
        int ge = e0 + e;
        A0[k * A0_PITCH + e] = (ge < E) ? rfv[(size_t)ge * NRBF + k] : 0.f;
    }
    for (int idx = t; idx < 64 * 32; idx += ETHR) {         // W0T
        int j = idx >> 5, k = idx & 31;
        Wb[k * 64 + j] = W0[idx];
    }
    for (int idx = t; idx < 128 * 64; idx += ETHR) {        // W1T (disjoint region)
        int j = idx >> 6, k = idx & 63;
        Wb[WB1_OFF + k * 128 + j] = W1[idx];
    }
    __syncthreads();

    int eg = t & 15;          // edge group: edges 4*eg .. 4*eg+3
    int jg = t >> 4;          // output group 0..31

    // ---- layer 1: 32 -> 64, thread tile 4e x 2j
    {
        float b_0 = Bs[2 * jg], b_1 = Bs[2 * jg + 1];
        float acc0[4], acc1[4];
#pragma unroll
        for (int i = 0; i < 4; i++) { acc0[i] = b_0; acc1[i] = b_1; }
#pragma unroll 8
        for (int k = 0; k < 32; k++) {
            float4 a4 = *(const float4*)&A0[k * A0_PITCH + 4 * eg];
            float2 w  = *(const float2*)&Wb[k * 64 + 2 * jg];
            acc0[0] += w.x * a4.x; acc0[1] += w.x * a4.y; acc0[2] += w.x * a4.z; acc0[3] += w.x * a4.w;
            acc1[0] += w.y * a4.x; acc1[1] += w.y * a4.y; acc1[2] += w.y * a4.z; acc1[3] += w.y * a4.w;
        }
#pragma unroll
        for (int i = 0; i < 4; i++) {
            A1[(2 * jg)     * A0_PITCH + 4 * eg + i] = silu_f(acc0[i]);
            A1[(2 * jg + 1) * A0_PITCH + 4 * eg + i] = silu_f(acc1[i]);
        }
    }
    __syncthreads();

    // ---- layer 2: 64 -> 128, thread tile 4e x 4j
    {
        int j0 = 4 * jg;
        float acc[4][4];
#pragma unroll
        for (int jj = 0; jj < 4; jj++) {
            float b = Bs[64 + j0 + jj];
#pragma unroll
            for (int i = 0; i < 4; i++) acc[jj][i] = b;
        }
#pragma unroll 4
        for (int k = 0; k < 64; k++) {
            float4 a4 = *(const float4*)&A1[k * A0_PITCH + 4 * eg];
            float4 w  = *(const float4*)&Wb[WB1_OFF + k * 128 + j0];
            acc[0][0] += w.x * a4.x; acc[0][1] += w.x * a4.y; acc[0][2] += w.x * a4.z; acc[0][3] += w.x * a4.w;
            acc[1][0] += w.y * a4.x; acc[1][1] += w.y * a4.y; acc[1][2] += w.y * a4.z; acc[1][3] += w.y * a4.w;
            acc[2][0] += w.z * a4.x; acc[2][1] += w.z * a4.y; acc[2][2] += w.z * a4.z; acc[2][3] += w.z * a4.w;
            acc[3][0] += w.w * a4.x; acc[3][1] += w.w * a4.y; acc[3][2] += w.w * a4.z; acc[3][3] += w.w * a4.w;
        }
#pragma unroll
        for (int jj = 0; jj < 4; jj++)
#pragma unroll
            for (int i = 0; i < 4; i++)
                A2[(j0 + jj) * A0_PITCH + 4 * eg + i] = silu_f(acc[jj][i]);
    }
    __syncthreads();   // A2 ready; all Wb (W0T/W1T) reads done

    // ---- layer 3: 128 -> 192, two passes of 96 outputs, thread tile 4e x 3j per pass
    float accL3[2][3][4];
#pragma unroll
    for (int p = 0; p < 2; p++) {
        // stage W2T half p: Wb[k*96 + jl] = W2[(96p+jl)*128 + k]
        for (int idx = t; idx < 96 * 128; idx += ETHR) {
            int jl = idx >> 7, k = idx & 127;
            Wb[k * 96 + jl] = W2[(size_t)(96 * p + jl) * 128 + k];
        }
        __syncthreads();

        int jl0 = 3 * jg;
#pragma unroll
        for (int jj = 0; jj < 3; jj++) {
            float b = Bs[192 + 96 * p + jl0 + jj];
#pragma unroll
            for (int i = 0; i < 4; i++) accL3[p][jj][i] = b;
        }
#pragma unroll 4
        for (int k = 0; k < 128; k++) {
            float4 a4 = *(const float4*)&A2[k * A0_PITCH + 4 * eg];
            float w0 = Wb[k * 96 + jl0];
            float w1 = Wb[k * 96 + jl0 + 1];
            float w2 = Wb[k * 96 + jl0 + 2];
            accL3[p][0][0] += w0 * a4.x; accL3[p][0][1] += w0 * a4.y; accL3[p][0][2] += w0 * a4.z; accL3[p][0][3] += w0 * a4.w;
            accL3[p][1][0] += w1 * a4.x; accL3[p][1][1] += w1 * a4.y; accL3[p][1][2] += w1 * a4.z; accL3[p][1][3] += w1 * a4.w;
            accL3[p][2][0] += w2 * a4.x; accL3[p][2][1] += w2 * a4.y; accL3[p][2][2] += w2 * a4.z; accL3[p][2][3] += w2 * a4.w;
        }
        __syncthreads();   // Wb reads (and for p=1, A2 reads) done
    }

    // ---- write R (overlays A region), R[e][j] = silu(h)*C[e]
    {
        float* R = sm + R_OFF;
#pragma unroll
        for (int p = 0; p < 2; p++) {
            int jb = 96 * p + 3 * jg;
#pragma unroll
            for (int jj = 0; jj < 3; jj++)
#pragma unroll
                for (int i = 0; i < 4; i++) {
                    int e = 4 * eg + i;
                    R[e * RPITCH + jb + jj] = silu_f(accL3[p][jj][i]) * Cs[e];
                }
        }
    }
    __syncthreads();

    // ---- scatter: msg_c = r_sel(c) * Y_c[src], atomically added into Msg[dst]
    {
        const float* R = sm + R_OFF;
        int warp = t >> 5, lane = t & 31;
        int sub = lane & 15;         // f-chunk (16 x float4 = 64 f)
        int half = lane >> 4;
#pragma unroll
        for (int pr = 0; pr < 2; pr++) {
            int el = warp * 4 + pr * 2 + half;
            int ge = e0 + el;
            if (ge < E) {
                int dst = pairs[ge];
                int src = pairs[E + ge];
                const float* yb = Y   + (size_t)src * CSTR;
                float*       mb = Msg + (size_t)dst * CSTR;
                int f0 = sub * 4;
#pragma unroll
                for (int c = 0; c < 9; c++) {
                    int ri = (c == 0) ? 0 : ((c < 4) ? 1 : 2);
                    float4 y4 = *(const float4*)&yb[c * 64 + f0];
                    const float* rr = &R[el * RPITCH + f0 * 3 + ri];
                    float4 m = make_float4(rr[0] * y4.x, rr[3] * y4.y, rr[6] * y4.z, rr[9] * y4.w);
                    red_v4(&mb[c * 64 + f0], m);
                }
            }
        }
    }
}

// ---------------------------------------------------------------- K5a: T = q*(M@Y + Y@M), normalize; in-place into Msg
__global__ void post_a(const float* __restrict__ Y, float* __restrict__ Msg,
                       const float* __restrict__ qraw, int N) {
    int t = blockIdx.x * blockDim.x + threadIdx.x;
    if (t >= N * FDIM) return;
    int n = t / FDIM, f = t % FDIM;
    const float* yp = Y   + (size_t)n * CSTR + f;
    float*       mp = Msg + (size_t)n * CSTR + f;
    float yc[9], mc[9];
#pragma unroll
    for (int c = 0; c < 9; c++) { yc[c] = yp[c * 64]; mc[c] = mp[c * 64]; }
    float Ym[3][3], Mm[3][3];
    comp2mat(yc, Ym);
    comp2mat(mc, Mm);
    float q = 1.0f + 0.1f * qraw[n];
    float T[3][3];
    float fr = 0.f;
#pragma unroll
    for (int i = 0; i < 3; i++)
#pragma unroll
        for (int j = 0; j < 3; j++) {
            float s = 0.f;
#pragma unroll
            for (int k = 0; k < 3; k++) s += Mm[i][k] * Ym[k][j] + Ym[i][k] * Mm[k][j];
            s *= q;
            T[i][j] = s;
            fr += s * s;
        }
    float inv = 1.0f / (fr + 1.0f);
    float tc[9];
    mat2comp(T, tc);
#pragma unroll
    for (int c = 0; c < 9; c++) mp[c * 64] = tc[c] * inv;
}

// ---------------------------------------------------------------- K5c: X' = Xn + dX + q * dX@dX
__global__ void finalize_k(const float* __restrict__ dXc, const float* __restrict__ Xnc,
                           const float* __restrict__ qraw, float* __restrict__ out, int N) {
    int t = blockIdx.x * blockDim.x + threadIdx.x;
    if (t >= N * FDIM) return;
    int n = t / FDIM, f = t % FDIM;
    const float* dp = dXc + (size_t)n * CSTR + f;
    const float* xp = Xnc + (size_t)n * CSTR + f;
    float dc[9], xc[9];
#pragma unroll
    for (int c = 0; c < 9; c++) { dc[c] = dp[c * 64]; xc[c] = xp[c * 64]; }
    float D[3][3], Xm[3][3];
    comp2mat(dc, D);
    comp2mat(xc, Xm);
    float q = 1.0f + 0.1f * qraw[n];
    float* o = out + (size_t)t * 9;
#pragma unroll
    for (int i = 0; i < 3; i++)
#pragma unroll
        for (int j = 0; j < 3; j++) {
            float p = 0.f;
#pragma unroll
            for (int k = 0; k < 3; k++) p += D[i][k] * D[k][j];
            o[i * 3 + j] = Xm[i][j] + D[i][j] + q * p;
        }
}

// ---------------------------------------------------------------- host
extern "C" void kernel_launch(void* const* d_in, const int* in_sizes, int n_in,
                              void* d_out, int out_size) {
    const float* X    = (const float*)d_in[0];
    const int*   prs  = (const int*)  d_in[1];
    const float* dij  = (const float*)d_in[2];
    const float* rfv  = (const float*)d_in[3];
    const float* q    = (const float*)d_in[4];
    const float* W0   = (const float*)d_in[5];
    const float* b0   = (const float*)d_in[6];
    const float* W1   = (const float*)d_in[7];
    const float* b1   = (const float*)d_in[8];
    const float* W2   = (const float*)d_in[9];
    const float* b2   = (const float*)d_in[10];
    const float* Wt   = (const float*)d_in[11];

    int N = in_sizes[4];          // atomic_charges length
    int E = in_sizes[2];          // d_ij length

    float *pXn, *pY, *pM;
    cudaGetSymbolAddress((void**)&pXn, g_Xn);
    cudaGetSymbolAddress((void**)&pY,  g_Y);
    cudaGetSymbolAddress((void**)&pM,  g_Mg);

    cudaFuncSetAttribute(edge_kernel, cudaFuncAttributeMaxDynamicSharedMemorySize, EDGE_SMEM);
    cudaFuncSetAttribute(mix_kernel,  cudaFuncAttributeMaxDynamicSharedMemorySize, MIX_SMEM);

    int nf_blocks = (N * FDIM + 255) / 256;

    atom_pre<<<nf_blocks, 256>>>(X, pXn, N);
    mix_kernel<<<(N + MIX_AB - 1) / MIX_AB, 256, MIX_SMEM>>>(pXn, pY, Wt, N);
    zero_kernel<<<2048, 256>>>((float4*)pM, N * (CSTR / 4));
    edge_kernel<<<(E + TE - 1) / TE, ETHR, EDGE_SMEM>>>(rfv, dij, prs,
                                                        W0, b0, W1, b1, W2, b2,
                                                        pY, pM, E);
    post_a<<<nf_blocks, 256>>>(pY, pM, q, N);
    mix_kernel<<<(N + MIX_AB - 1) / MIX_AB, 256, MIX_SMEM>>>(pM, pY, Wt + 3 * 64 * 64, N);
    finalize_k<<<nf_blocks, 256>>>(pY, pXn, q, (float*)d_out, N);
}

// round 13
// speedup vs baseline: 2.0908x; 1.3315x over previous
#include <cuda_runtime.h>
#include <cstdint>

#define FDIM  64
#define NRBF  32
#define NC    9
#define CSTR  (FDIM * NC)   // 576 floats per atom (compressed irrep form)

#define MAXN  24000

// Scratch (no cudaMalloc allowed)
__device__ float g_Xn[MAXN * CSTR];   // normalized X, compressed
__device__ float g_Y [MAXN * CSTR];   // mixed Y (then reused for dX)
__device__ float g_Mg[MAXN * CSTR];   // message accumulator (then reused for T)

// ---------------------------------------------------------------- helpers
__device__ __forceinline__ float silu_f(float x) {
    return __fdividef(x, 1.0f + __expf(-x));
}

__device__ __forceinline__ void red_v4(float* addr, float4 v) {
    asm volatile("red.global.add.v4.f32 [%0], {%1,%2,%3,%4};"
                 :: "l"(addr), "f"(v.x), "f"(v.y), "f"(v.z), "f"(v.w)
                 : "memory");
}

// comp order: [c0, a01, a02, a12, s00, s11, s01, s02, s12]
__device__ __forceinline__ void comp2mat(const float c[9], float t[3][3]) {
    t[0][0] = c[0] + c[4];
    t[1][1] = c[0] + c[5];
    t[2][2] = c[0] - c[4] - c[5];
    t[0][1] = c[6] + c[1];  t[1][0] = c[6] - c[1];
    t[0][2] = c[7] + c[2];  t[2][0] = c[7] - c[2];
    t[1][2] = c[8] + c[3];  t[2][1] = c[8] - c[3];
}

__device__ __forceinline__ void mat2comp(const float t[3][3], float c[9]) {
    float c0 = (t[0][0] + t[1][1] + t[2][2]) * (1.0f / 3.0f);
    c[0] = c0;
    c[1] = 0.5f * (t[0][1] - t[1][0]);
    c[2] = 0.5f * (t[0][2] - t[2][0]);
    c[3] = 0.5f * (t[1][2] - t[2][1]);
    c[4] = t[0][0] - c0;
    c[5] = t[1][1] - c0;
    c[6] = 0.5f * (t[0][1] + t[1][0]);
    c[7] = 0.5f * (t[0][2] + t[2][0]);
    c[8] = 0.5f * (t[1][2] + t[2][1]);
}

// ---------------------------------------------------------------- zero scratch
__global__ void zero_kernel(float4* __restrict__ p, int n4) {
    int i = blockIdx.x * blockDim.x + threadIdx.x;
    int stride = gridDim.x * blockDim.x;
    float4 z = make_float4(0.f, 0.f, 0.f, 0.f);
    for (; i < n4; i += stride) p[i] = z;
}

// ---------------------------------------------------------------- K1: normalize + decompose
__global__ void atom_pre(const float* __restrict__ X, float* __restrict__ Xn, int N) {
    int t = blockIdx.x * blockDim.x + threadIdx.x;
    if (t >= N * FDIM) return;
    int n = t / FDIM, f = t % FDIM;
    const float* p = X + (size_t)t * 9;
    float m[9];
#pragma unroll
    for (int i = 0; i < 9; i++) m[i] = p[i];
    float tn = 0.f;
#pragma unroll
    for (int i = 0; i < 9; i++) tn += m[i] * m[i];
    float inv = 1.0f / (tn + 1.0f);
#pragma unroll
    for (int i = 0; i < 9; i++) m[i] *= inv;
    float c0  = (m[0] + m[4] + m[8]) * (1.0f / 3.0f);
    float a01 = 0.5f * (m[1] - m[3]);
    float a02 = 0.5f * (m[2] - m[6]);
    float a12 = 0.5f * (m[5] - m[7]);
    float s00 = m[0] - c0;
    float s11 = m[4] - c0;
    float s01 = 0.5f * (m[1] + m[3]);
    float s02 = 0.5f * (m[2] + m[6]);
    float s12 = 0.5f * (m[5] + m[7]);
    float* o = Xn + (size_t)n * CSTR + f;
    o[0 * 64] = c0;  o[1 * 64] = a01; o[2 * 64] = a02; o[3 * 64] = a12;
    o[4 * 64] = s00; o[5 * 64] = s11; o[6 * 64] = s01; o[7 * 64] = s02; o[8 * 64] = s12;
}

// ---------------------------------------------------------------- K2/K5b: channel mix (9 subspace GEMMs)
#define MIX_AB    16
#define MIX_PAD   584
#define MIX_SMEM  ((3 * 4096 + MIX_AB * MIX_PAD) * 4)

__global__ void __launch_bounds__(256) mix_kernel(const float* __restrict__ In,
                                                  float* __restrict__ Out,
                                                  const float* __restrict__ W, int N) {
    extern __shared__ float sm[];
    float* WT  = sm;                 // 3 * [f][g] 64x64
    float* InS = sm + 3 * 4096;      // 16 x MIX_PAD
    int t  = threadIdx.x;
    int nb = blockIdx.x * MIX_AB;

    for (int idx = t; idx < 3 * 4096; idx += 256) {
        int mtx = idx >> 12, rem = idx & 4095;
        int g = rem >> 6, f = rem & 63;
        WT[mtx * 4096 + f * 64 + g] = W[idx];
    }
    for (int idx = t; idx < MIX_AB * CSTR; idx += 256) {
        int a = idx / CSTR, off = idx % CSTR;
        int n = nb + a;
        InS[a * MIX_PAD + off] = (n < N) ? In[(size_t)n * CSTR + off] : 0.f;
    }
    __syncthreads();

    int a = t >> 4, g0 = (t & 15) * 4;
    float acc[9][4];
#pragma unroll
    for (int c = 0; c < 9; c++)
#pragma unroll
        for (int i = 0; i < 4; i++) acc[c][i] = 0.f;

    const float* ip = InS + a * MIX_PAD;
#pragma unroll 4
    for (int f = 0; f < 64; f++) {
        float4 w0 = *(const float4*)&WT[         f * 64 + g0];
        float4 w1 = *(const float4*)&WT[4096  +  f * 64 + g0];
        float4 w2 = *(const float4*)&WT[8192  +  f * 64 + g0];
        float x;
        x = ip[0 * 64 + f];
        acc[0][0] += w0.x * x; acc[0][1] += w0.y * x; acc[0][2] += w0.z * x; acc[0][3] += w0.w * x;
#pragma unroll
        for (int c = 1; c < 4; c++) {
            x = ip[c * 64 + f];
            acc[c][0] += w1.x * x; acc[c][1] += w1.y * x; acc[c][2] += w1.z * x; acc[c][3] += w1.w * x;
        }
#pragma unroll
        for (int c = 4; c < 9; c++) {
            x = ip[c * 64 + f];
            acc[c][0] += w2.x * x; acc[c][1] += w2.y * x; acc[c][2] += w2.z * x; acc[c][3] += w2.w * x;
        }
    }
    int n = nb + a;
    if (n < N) {
#pragma unroll
        for (int c = 0; c < 9; c++) {
            float4 v = make_float4(acc[c][0], acc[c][1], acc[c][2], acc[c][3]);
            *(float4*)&Out[(size_t)n * CSTR + c * 64 + g0] = v;
        }
    }
}

// ---------------------------------------------------------------- K3: fused edge MLP + message scatter
// smem layout (floats):
//   [0, 12416)        Wb : W0T (2048) + W1T at 2048 (8192); later W2T halves in packed
//                     layout Wb[jg*388 + k*3 + c] (32 x 388 = 12416)
//   [12416, 27648)    A0/A1/A2 activations (pitch 68); later overlaid by R (64 x 200)
//   [27648, 27712)    Cs (cutoff per edge)
//   [27712, 28096)    Bs (biases 64+128+192)
#define TE        64
#define ETHR      512
#define WB1_OFF   2048
#define W2PITCH   388
#define A0_OFF    12416
#define A0_PITCH  68
#define A1_OFF    (A0_OFF + 32 * A0_PITCH)
#define A2_OFF    (A1_OFF + 64 * A0_PITCH)
#define R_OFF     A0_OFF
#define CS_OFF    (A2_OFF + 128 * A0_PITCH)
#define BS_OFF    (CS_OFF + 64)
#define RPITCH    200
#define EDGE_SMEM ((BS_OFF + 384) * 4)   // 112384 B -> still 2 CTAs/SM

__global__ void __launch_bounds__(ETHR, 2) edge_kernel(
    const float* __restrict__ rfv, const float* __restrict__ dij,
    const int* __restrict__ pairs,
    const float* __restrict__ W0, const float* __restrict__ b0,
    const float* __restrict__ W1, const float* __restrict__ b1,
    const float* __restrict__ W2, const float* __restrict__ b2,
    const float* __restrict__ Y, float* __restrict__ Msg, int E)
{
    extern __shared__ float sm[];
    float* Wb = sm;
    float* A0 = sm + A0_OFF;
    float* A1 = sm + A1_OFF;
    float* A2 = sm + A2_OFF;
    float* Cs = sm + CS_OFF;
    float* Bs = sm + BS_OFF;

    int t  = threadIdx.x;
    int e0 = blockIdx.x * TE;

    if (t < 384) {
        float v = (t < 64) ? b0[t] : ((t < 192) ? b1[t - 64] : b2[t - 192]);
        Bs[t] = v;
    }
    if (t < TE) {
        int ge = e0 + t;
        float d = (ge < E) ? dij[ge] : 2.0f;
        Cs[t] = (d < 1.0f) ? 0.5f * (cospif(d) + 1.0f) : 0.0f;
    }
    for (int idx = t; idx < TE * NRBF; idx += ETHR) {       // rfv -> A0[k][e]
        int e = idx >> 5, k = idx & 31;
        int ge = e0 + e;
        A0[k * A0_PITCH + e] = (ge < E) ? rfv[(size_t)ge * NRBF + k] : 0.f;
    }
    for (int idx = t; idx < 64 * 32; idx += ETHR) {         // W0T
        int j = idx >> 5, k = idx & 31;
        Wb[k * 64 + j] = W0[idx];
    }
    for (int idx = t; idx < 128 * 64; idx += ETHR) {        // W1T (disjoint region)
        int j = idx >> 6, k = idx & 63;
        Wb[WB1_OFF + k * 128 + j] = W1[idx];
    }
    __syncthreads();

    int eg = t & 15;          // edge group: edges 4*eg .. 4*eg+3
    int jg = t >> 4;          // output group 0..31

    // ---- layer 1: 32 -> 64, thread tile 4e x 2j
    {
        float b_0 = Bs[2 * jg], b_1 = Bs[2 * jg + 1];
        float acc0[4], acc1[4];
#pragma unroll
        for (int i = 0; i < 4; i++) { acc0[i] = b_0; acc1[i] = b_1; }
#pragma unroll 8
        for (int k = 0; k < 32; k++) {
            float4 a4 = *(const float4*)&A0[k * A0_PITCH + 4 * eg];
            float2 w  = *(const float2*)&Wb[k * 64 + 2 * jg];
            acc0[0] += w.x * a4.x; acc0[1] += w.x * a4.y; acc0[2] += w.x * a4.z; acc0[3] += w.x * a4.w;
            acc1[0] += w.y * a4.x; acc1[1] += w.y * a4.y; acc1[2] += w.y * a4.z; acc1[3] += w.y * a4.w;
        }
#pragma unroll
        for (int i = 0; i < 4; i++) {
            A1[(2 * jg)     * A0_PITCH + 4 * eg + i] = silu_f(acc0[i]);
            A1[(2 * jg + 1) * A0_PITCH + 4 * eg + i] = silu_f(acc1[i]);
        }
    }
    __syncthreads();

    // ---- layer 2: 64 -> 128, thread tile 4e x 4j
    {
        int j0 = 4 * jg;
        float acc[4][4];
#pragma unroll
        for (int jj = 0; jj < 4; jj++) {
            float b = Bs[64 + j0 + jj];
#pragma unroll
            for (int i = 0; i < 4; i++) acc[jj][i] = b;
        }
#pragma unroll 4
        for (int k = 0; k < 64; k++) {
            float4 a4 = *(const float4*)&A1[k * A0_PITCH + 4 * eg];
            float4 w  = *(const float4*)&Wb[WB1_OFF + k * 128 + j0];
            acc[0][0] += w.x * a4.x; acc[0][1] += w.x * a4.y; acc[0][2] += w.x * a4.z; acc[0][3] += w.x * a4.w;
            acc[1][0] += w.y * a4.x; acc[1][1] += w.y * a4.y; acc[1][2] += w.y * a4.z; acc[1][3] += w.y * a4.w;
            acc[2][0] += w.z * a4.x; acc[2][1] += w.z * a4.y; acc[2][2] += w.z * a4.z; acc[2][3] += w.z * a4.w;
            acc[3][0] += w.w * a4.x; acc[3][1] += w.w * a4.y; acc[3][2] += w.w * a4.z; acc[3][3] += w.w * a4.w;
        }
#pragma unroll
        for (int jj = 0; jj < 4; jj++)
#pragma unroll
            for (int i = 0; i < 4; i++)
                A2[(j0 + jj) * A0_PITCH + 4 * eg + i] = silu_f(acc[jj][i]);
    }
    __syncthreads();   // A2 ready; all Wb (W0T/W1T) reads done

    // ---- layer 3: 128 -> 192, two passes of 96 outputs, thread tile 4e x 3j.
    // W2T packed per-jg: Wb[jg*388 + k*3 + c] so a thread's 12 weights for a
    // 4-k block are 3 aligned float4 loads (was 12 scalar LDS).
    float accL3[2][3][4];
#pragma unroll
    for (int p = 0; p < 2; p++) {
        for (int idx = t; idx < 32 * 128 * 3; idx += ETHR) {
            int jg2 = idx / 384;
            int rem = idx - jg2 * 384;
            int c   = rem >> 7;
            int k   = rem & 127;
            Wb[jg2 * W2PITCH + k * 3 + c] = W2[(size_t)(96 * p + 3 * jg2 + c) * 128 + k];
        }
        __syncthreads();

#pragma unroll
        for (int jj = 0; jj < 3; jj++) {
            float b = Bs[192 + 96 * p + 3 * jg + jj];
#pragma unroll
            for (int i = 0; i < 4; i++) accL3[p][jj][i] = b;
        }
        const float* wbase = &Wb[jg * W2PITCH];
#pragma unroll 2
        for (int kb = 0; kb < 128; kb += 4) {
            float4 w0 = *(const float4*)&wbase[kb * 3];
            float4 w1 = *(const float4*)&wbase[kb * 3 + 4];
            float4 w2 = *(const float4*)&wbase[kb * 3 + 8];
            float4 a0 = *(const float4*)&A2[(kb + 0) * A0_PITCH + 4 * eg];
            float4 a1 = *(const float4*)&A2[(kb + 1) * A0_PITCH + 4 * eg];
            // k = kb   : c0=w0.x c1=w0.y c2=w0.z
            accL3[p][0][0] += w0.x*a0.x; accL3[p][0][1] += w0.x*a0.y; accL3[p][0][2] += w0.x*a0.z; accL3[p][0][3] += w0.x*a0.w;
            accL3[p][1][0] += w0.y*a0.x; accL3[p][1][1] += w0.y*a0.y; accL3[p][1][2] += w0.y*a0.z; accL3[p][1][3] += w0.y*a0.w;
            accL3[p][2][0] += w0.z*a0.x; accL3[p][2][1] += w0.z*a0.y; accL3[p][2][2] += w0.z*a0.z; accL3[p][2][3] += w0.z*a0.w;
            // k = kb+1 : c0=w0.w c1=w1.x c2=w1.y
            accL3[p][0][0] += w0.w*a1.x; accL3[p][0][1] += w0.w*a1.y; accL3[p][0][2] += w0.w*a1.z; accL3[p][0][3] += w0.w*a1.w;
            accL3[p][1][0] += w1.x*a1.x; accL3[p][1][1] += w1.x*a1.y; accL3[p][1][2] += w1.x*a1.z; accL3[p][1][3] += w1.x*a1.w;
            accL3[p][2][0] += w1.y*a1.x; accL3[p][2][1] += w1.y*a1.y; accL3[p][2][2] += w1.y*a1.z; accL3[p][2][3] += w1.y*a1.w;
            float4 a2 = *(const float4*)&A2[(kb + 2) * A0_PITCH + 4 * eg];
            float4 a3 = *(const float4*)&A2[(kb + 3) * A0_PITCH + 4 * eg];
            // k = kb+2 : c0=w1.z c1=w1.w c2=w2.x
            accL3[p][0][0] += w1.z*a2.x; accL3[p][0][1] += w1.z*a2.y; accL3[p][0][2] += w1.z*a2.z; accL3[p][0][3] += w1.z*a2.w;
            accL3[p][1][0] += w1.w*a2.x; accL3[p][1][1] += w1.w*a2.y; accL3[p][1][2] += w1.w*a2.z; accL3[p][1][3] += w1.w*a2.w;
            accL3[p][2][0] += w2.x*a2.x; accL3[p][2][1] += w2.x*a2.y; accL3[p][2][2] += w2.x*a2.z; accL3[p][2][3] += w2.x*a2.w;
            // k = kb+3 : c0=w2.y c1=w2.z c2=w2.w
            accL3[p][0][0] += w2.y*a3.x; accL3[p][0][1] += w2.y*a3.y; accL3[p][0][2] += w2.y*a3.z; accL3[p][0][3] += w2.y*a3.w;
            accL3[p][1][0] += w2.z*a3.x; accL3[p][1][1] += w2.z*a3.y; accL3[p][1][2] += w2.z*a3.z; accL3[p][1][3] += w2.z*a3.w;
            accL3[p][2][0] += w2.w*a3.x; accL3[p][2][1] += w2.w*a3.y; accL3[p][2][2] += w2.w*a3.z; accL3[p][2][3] += w2.w*a3.w;
        }
        __syncthreads();   // Wb reads (and for p=1, A2 reads) done
    }

    // ---- write R (overlays A region), R[e][j] = silu(h)*C[e]
    {
        float* R = sm + R_OFF;
#pragma unroll
        for (int p = 0; p < 2; p++) {
            int jb = 96 * p + 3 * jg;
#pragma unroll
            for (int jj = 0; jj < 3; jj++)
#pragma unroll
                for (int i = 0; i < 4; i++) {
                    int e = 4 * eg + i;
                    R[e * RPITCH + jb + jj] = silu_f(accL3[p][jj][i]) * Cs[e];
                }
        }
    }
    __syncthreads();

    // ---- scatter: msg_c = r_sel(c) * Y_c[src], atomically added into Msg[dst]
    // The 12 R values a thread needs (3 ri x 4 f) are contiguous: 3 float4 loads
    // reused across all 9 c (was 72 scalar LDS).
    {
        const float* R = sm + R_OFF;
        int warp = t >> 5, lane = t & 31;
        int sub = lane & 15;         // f-chunk (16 x float4 = 64 f)
        int half = lane >> 4;
#pragma unroll
        for (int pr = 0; pr < 2; pr++) {
            int el = warp * 4 + pr * 2 + half;
            int ge = e0 + el;
            if (ge < E) {
                int dst = pairs[ge];
                int src = pairs[E + ge];
                const float* yb = Y   + (size_t)src * CSTR;
                float*       mb = Msg + (size_t)dst * CSTR;
                int f0 = sub * 4;
                const float* rr = &R[el * RPITCH + f0 * 3];
                float4 r0 = *(const float4*)&rr[0];
                float4 r1 = *(const float4*)&rr[4];
                float4 r2 = *(const float4*)&rr[8];
                // ri-selected scale per f in {f0..f0+3}
                float s0x = r0.x, s0y = r0.w, s0z = r1.z, s0w = r2.y;  // ri = 0
                float s1x = r0.y, s1y = r1.x, s1z = r1.w, s1w = r2.z;  // ri = 1
                float s2x = r0.z, s2y = r1.y, s2z = r2.x, s2w = r2.w;  // ri = 2
#pragma unroll
                for (int c = 0; c < 9; c++) {
                    float4 y4 = *(const float4*)&yb[c * 64 + f0];
                    float4 m;
                    if (c == 0) {
                        m = make_float4(s0x * y4.x, s0y * y4.y, s0z * y4.z, s0w * y4.w);
                    } else if (c < 4) {
                        m = make_float4(s1x * y4.x, s1y * y4.y, s1z * y4.z, s1w * y4.w);
                    } else {
                        m = make_float4(s2x * y4.x, s2y * y4.y, s2z * y4.z, s2w * y4.w);
                    }
                    red_v4(&mb[c * 64 + f0], m);
                }
            }
        }
    }
}

// ---------------------------------------------------------------- K5a: T = q*(M@Y + Y@M), normalize; in-place into Msg
__global__ void post_a(const float* __restrict__ Y, float* __restrict__ Msg,
                       const float* __restrict__ qraw, int N) {
    int t = blockIdx.x * blockDim.x + threadIdx.x;
    if (t >= N * FDIM) return;
    int n = t / FDIM, f = t % FDIM;
    const float* yp = Y   + (size_t)n * CSTR + f;
    float*       mp = Msg + (size_t)n * CSTR + f;
    float yc[9], mc[9];
#pragma unroll
    for (int c = 0; c < 9; c++) { yc[c] = yp[c * 64]; mc[c] = mp[c * 64]; }
    float Ym[3][3], Mm[3][3];
    comp2mat(yc, Ym);
    comp2mat(mc, Mm);
    float q = 1.0f + 0.1f * qraw[n];
    float T[3][3];
    float fr = 0.f;
#pragma unroll
    for (int i = 0; i < 3; i++)
#pragma unroll
        for (int j = 0; j < 3; j++) {
            float s = 0.f;
#pragma unroll
            for (int k = 0; k < 3; k++) s += Mm[i][k] * Ym[k][j] + Ym[i][k] * Mm[k][j];
            s *= q;
            T[i][j] = s;
            fr += s * s;
        }
    float inv = 1.0f / (fr + 1.0f);
    float tc[9];
    mat2comp(T, tc);
#pragma unroll
    for (int c = 0; c < 9; c++) mp[c * 64] = tc[c] * inv;
}

// ---------------------------------------------------------------- K5c: X' = Xn + dX + q * dX@dX
__global__ void finalize_k(const float* __restrict__ dXc, const float* __restrict__ Xnc,
                           const float* __restrict__ qraw, float* __restrict__ out, int N) {
    int t = blockIdx.x * blockDim.x + threadIdx.x;
    if (t >= N * FDIM) return;
    int n = t / FDIM, f = t % FDIM;
    const float* dp = dXc + (size_t)n * CSTR + f;
    const float* xp = Xnc + (size_t)n * CSTR + f;
    float dc[9], xc[9];
#pragma unroll
    for (int c = 0; c < 9; c++) { dc[c] = dp[c * 64]; xc[c] = xp[c * 64]; }
    float D[3][3], Xm[3][3];
    comp2mat(dc, D);
    comp2mat(xc, Xm);
    float q = 1.0f + 0.1f * qraw[n];
    float* o = out + (size_t)t * 9;
#pragma unroll
    for (int i = 0; i < 3; i++)
#pragma unroll
        for (int j = 0; j < 3; j++) {
            float p = 0.f;
#pragma unroll
            for (int k = 0; k < 3; k++) p += D[i][k] * D[k][j];
            o[i * 3 + j] = Xm[i][j] + D[i][j] + q * p;
        }
}

// ---------------------------------------------------------------- host
extern "C" void kernel_launch(void* const* d_in, const int* in_sizes, int n_in,
                              void* d_out, int out_size) {
    const float* X    = (const float*)d_in[0];
    const int*   prs  = (const int*)  d_in[1];
    const float* dij  = (const float*)d_in[2];
    const float* rfv  = (const float*)d_in[3];
    const float* q    = (const float*)d_in[4];
    const float* W0   = (const float*)d_in[5];
    const float* b0   = (const float*)d_in[6];
    const float* W1   = (const float*)d_in[7];
    const float* b1   = (const float*)d_in[8];
    const float* W2   = (const float*)d_in[9];
    const float* b2   = (const float*)d_in[10];
    const float* Wt   = (const float*)d_in[11];

    int N = in_sizes[4];          // atomic_charges length
    int E = in_sizes[2];          // d_ij length

    float *pXn, *pY, *pM;
    cudaGetSymbolAddress((void**)&pXn, g_Xn);
    cudaGetSymbolAddress((void**)&pY,  g_Y);
    cudaGetSymbolAddress((void**)&pM,  g_Mg);

    cudaFuncSetAttribute(edge_kernel, cudaFuncAttributeMaxDynamicSharedMemorySize, EDGE_SMEM);
    cudaFuncSetAttribute(mix_kernel,  cudaFuncAttributeMaxDynamicSharedMemorySize, MIX_SMEM);

    int nf_blocks = (N * FDIM + 255) / 256;

    atom_pre<<<nf_blocks, 256>>>(X, pXn, N);
    mix_kernel<<<(N + MIX_AB - 1) / MIX_AB, 256, MIX_SMEM>>>(pXn, pY, Wt, N);
    zero_kernel<<<2048, 256>>>((float4*)pM, N * (CSTR / 4));
    edge_kernel<<<(E + TE - 1) / TE, ETHR, EDGE_SMEM>>>(rfv, dij, prs,
                                                        W0, b0, W1, b1, W2, b2,
                                                        pY, pM, E);
    post_a<<<nf_blocks, 256>>>(pY, pM, q, N);
    mix_kernel<<<(N + MIX_AB - 1) / MIX_AB, 256, MIX_SMEM>>>(pM, pY, Wt + 3 * 64 * 64, N);
    finalize_k<<<nf_blocks, 256>>>(pY, pXn, q, (float*)d_out, N);
}

// round 14
// speedup vs baseline: 2.1648x; 1.0354x over previous
#include <cuda_runtime.h>
#include <cstdint>

#define FDIM  64
#define NRBF  32
#define NC    9
#define CSTR  (FDIM * NC)   // 576 floats per atom (compressed irrep form)

#define MAXN  24000

// Scratch (no cudaMalloc allowed)
__device__ float g_Xn[MAXN * CSTR];   // normalized X, compressed
__device__ float g_Y [MAXN * CSTR];   // mixed Y
__device__ float g_Mg[MAXN * CSTR];   // message accumulator

// ---------------------------------------------------------------- helpers
__device__ __forceinline__ float silu_f(float x) {
    return __fdividef(x, 1.0f + __expf(-x));
}

__device__ __forceinline__ void red_v4(float* addr, float4 v) {
    asm volatile("red.global.add.v4.f32 [%0], {%1,%2,%3,%4};"
                 :: "l"(addr), "f"(v.x), "f"(v.y), "f"(v.z), "f"(v.w)
                 : "memory");
}

// comp order: [c0, a01, a02, a12, s00, s11, s01, s02, s12]
__device__ __forceinline__ void comp2mat(const float c[9], float t[3][3]) {
    t[0][0] = c[0] + c[4];
    t[1][1] = c[0] + c[5];
    t[2][2] = c[0] - c[4] - c[5];
    t[0][1] = c[6] + c[1];  t[1][0] = c[6] - c[1];
    t[0][2] = c[7] + c[2];  t[2][0] = c[7] - c[2];
    t[1][2] = c[8] + c[3];  t[2][1] = c[8] - c[3];
}

__device__ __forceinline__ void mat2comp(const float t[3][3], float c[9]) {
    float c0 = (t[0][0] + t[1][1] + t[2][2]) * (1.0f / 3.0f);
    c[0] = c0;
    c[1] = 0.5f * (t[0][1] - t[1][0]);
    c[2] = 0.5f * (t[0][2] - t[2][0]);
    c[3] = 0.5f * (t[1][2] - t[2][1]);
    c[4] = t[0][0] - c0;
    c[5] = t[1][1] - c0;
    c[6] = 0.5f * (t[0][1] + t[1][0]);
    c[7] = 0.5f * (t[0][2] + t[2][0]);
    c[8] = 0.5f * (t[1][2] + t[2][1]);
}

// ---------------------------------------------------------------- zero scratch
__global__ void zero_kernel(float4* __restrict__ p, int n4) {
    int i = blockIdx.x * blockDim.x + threadIdx.x;
    int stride = gridDim.x * blockDim.x;
    float4 z = make_float4(0.f, 0.f, 0.f, 0.f);
    for (; i < n4; i += stride) p[i] = z;
}

// ---------------------------------------------------------------- mix kernels (fused)
#define MIX_AB    16
#define MIX_PAD   584
#define MIX_SMEM  ((3 * 4096 + MIX_AB * MIX_PAD) * 4)

// K1+K2 fused: normalize+decompose X inline, GEMM, write Y (and Xn for the residual)
__global__ void __launch_bounds__(256) mix1_fused(const float* __restrict__ X,
                                                  float* __restrict__ Xn,
                                                  float* __restrict__ Out,
                                                  const float* __restrict__ W, int N) {
    extern __shared__ float sm[];
    float* WT  = sm;                 // 3 * [f][g] 64x64
    float* InS = sm + 3 * 4096;      // 16 x MIX_PAD
    int t  = threadIdx.x;
    int nb = blockIdx.x * MIX_AB;

    for (int idx = t; idx < 3 * 4096; idx += 256) {
        int mtx = idx >> 12, rem = idx & 4095;
        int g = rem >> 6, f = rem & 63;
        WT[mtx * 4096 + f * 64 + g] = W[idx];
    }
    // fused atom_pre: per (atom, f) normalize + decompose -> InS (+ Xn for later)
    for (int i = t; i < MIX_AB * FDIM; i += 256) {
        int a = i >> 6, f = i & 63;
        int n = nb + a;
        float c[9];
        if (n < N) {
            const float* p = X + ((size_t)n * FDIM + f) * 9;
            float m[9];
#pragma unroll
            for (int j = 0; j < 9; j++) m[j] = p[j];
            float tn = 0.f;
#pragma unroll
            for (int j = 0; j < 9; j++) tn += m[j] * m[j];
            float inv = 1.0f / (tn + 1.0f);
#pragma unroll
            for (int j = 0; j < 9; j++) m[j] *= inv;
            c[0] = (m[0] + m[4] + m[8]) * (1.0f / 3.0f);
            c[1] = 0.5f * (m[1] - m[3]);
            c[2] = 0.5f * (m[2] - m[6]);
            c[3] = 0.5f * (m[5] - m[7]);
            c[4] = m[0] - c[0];
            c[5] = m[4] - c[0];
            c[6] = 0.5f * (m[1] + m[3]);
            c[7] = 0.5f * (m[2] + m[6]);
            c[8] = 0.5f * (m[5] + m[7]);
            float* o = Xn + (size_t)n * CSTR + f;
#pragma unroll
            for (int cc = 0; cc < 9; cc++) o[cc * 64] = c[cc];
        } else {
#pragma unroll
            for (int cc = 0; cc < 9; cc++) c[cc] = 0.f;
        }
#pragma unroll
        for (int cc = 0; cc < 9; cc++) InS[a * MIX_PAD + cc * 64 + f] = c[cc];
    }
    __syncthreads();

    int a = t >> 4, g0 = (t & 15) * 4;
    float acc[9][4];
#pragma unroll
    for (int c = 0; c < 9; c++)
#pragma unroll
        for (int i = 0; i < 4; i++) acc[c][i] = 0.f;

    const float* ip = InS + a * MIX_PAD;
#pragma unroll 4
    for (int f = 0; f < 64; f++) {
        float4 w0 = *(const float4*)&WT[         f * 64 + g0];
        float4 w1 = *(const float4*)&WT[4096  +  f * 64 + g0];
        float4 w2 = *(const float4*)&WT[8192  +  f * 64 + g0];
        float x;
        x = ip[0 * 64 + f];
        acc[0][0] += w0.x * x; acc[0][1] += w0.y * x; acc[0][2] += w0.z * x; acc[0][3] += w0.w * x;
#pragma unroll
        for (int c = 1; c < 4; c++) {
            x = ip[c * 64 + f];
            acc[c][0] += w1.x * x; acc[c][1] += w1.y * x; acc[c][2] += w1.z * x; acc[c][3] += w1.w * x;
        }
#pragma unroll
        for (int c = 4; c < 9; c++) {
            x = ip[c * 64 + f];
            acc[c][0] += w2.x * x; acc[c][1] += w2.y * x; acc[c][2] += w2.z * x; acc[c][3] += w2.w * x;
        }
    }
    int n = nb + a;
    if (n < N) {
#pragma unroll
        for (int c = 0; c < 9; c++) {
            float4 v = make_float4(acc[c][0], acc[c][1], acc[c][2], acc[c][3]);
            *(float4*)&Out[(size_t)n * CSTR + c * 64 + g0] = v;
        }
    }
}

// K5a+K5b+K5c fused: T = q(MY+YM)/normp1 inline; GEMM -> dX; epilogue writes
// X' = Xn + dX + q dX@dX directly to out.
__global__ void __launch_bounds__(256) mix2_fused(const float* __restrict__ Y,
                                                  const float* __restrict__ Msg,
                                                  const float* __restrict__ Xn,
                                                  const float* __restrict__ qraw,
                                                  float* __restrict__ out,
                                                  const float* __restrict__ W, int N) {
    extern __shared__ float sm[];
    float* WT  = sm;
    float* InS = sm + 3 * 4096;
    int t  = threadIdx.x;
    int nb = blockIdx.x * MIX_AB;

    for (int idx = t; idx < 3 * 4096; idx += 256) {
        int mtx = idx >> 12, rem = idx & 4095;
        int g = rem >> 6, f = rem & 63;
        WT[mtx * 4096 + f * 64 + g] = W[idx];
    }
    // fused post_a: per (atom, f) compute normalized T from Msg & Y -> InS
    for (int i = t; i < MIX_AB * FDIM; i += 256) {
        int a = i >> 6, f = i & 63;
        int n = nb + a;
        float tc[9];
        if (n < N) {
            const float* yp = Y   + (size_t)n * CSTR + f;
            const float* mp = Msg + (size_t)n * CSTR + f;
            float yc[9], mc[9];
#pragma unroll
            for (int cc = 0; cc < 9; cc++) { yc[cc] = yp[cc * 64]; mc[cc] = mp[cc * 64]; }
            float Ym[3][3], Mm[3][3];
            comp2mat(yc, Ym);
            comp2mat(mc, Mm);
            float q = 1.0f + 0.1f * qraw[n];
            float T[3][3];
            float fr = 0.f;
#pragma unroll
            for (int r = 0; r < 3; r++)
#pragma unroll
                for (int cc = 0; cc < 3; cc++) {
                    float s = 0.f;
#pragma unroll
                    for (int k = 0; k < 3; k++) s += Mm[r][k] * Ym[k][cc] + Ym[r][k] * Mm[k][cc];
                    s *= q;
                    T[r][cc] = s;
                    fr += s * s;
                }
            float inv = 1.0f / (fr + 1.0f);
            mat2comp(T, tc);
#pragma unroll
            for (int cc = 0; cc < 9; cc++) tc[cc] *= inv;
        } else {
#pragma unroll
            for (int cc = 0; cc < 9; cc++) tc[cc] = 0.f;
        }
#pragma unroll
        for (int cc = 0; cc < 9; cc++) InS[a * MIX_PAD + cc * 64 + f] = tc[cc];
    }
    __syncthreads();

    int a = t >> 4, g0 = (t & 15) * 4;
    float acc[9][4];
#pragma unroll
    for (int c = 0; c < 9; c++)
#pragma unroll
        for (int i = 0; i < 4; i++) acc[c][i] = 0.f;

    const float* ip = InS + a * MIX_PAD;
#pragma unroll 4
    for (int f = 0; f < 64; f++) {
        float4 w0 = *(const float4*)&WT[         f * 64 + g0];
        float4 w1 = *(const float4*)&WT[4096  +  f * 64 + g0];
        float4 w2 = *(const float4*)&WT[8192  +  f * 64 + g0];
        float x;
        x = ip[0 * 64 + f];
        acc[0][0] += w0.x * x; acc[0][1] += w0.y * x; acc[0][2] += w0.z * x; acc[0][3] += w0.w * x;
#pragma unroll
        for (int c = 1; c < 4; c++) {
            x = ip[c * 64 + f];
            acc[c][0] += w1.x * x; acc[c][1] += w1.y * x; acc[c][2] += w1.z * x; acc[c][3] += w1.w * x;
        }
#pragma unroll
        for (int c = 4; c < 9; c++) {
            x = ip[c * 64 + f];
            acc[c][0] += w2.x * x; acc[c][1] += w2.y * x; acc[c][2] += w2.z * x; acc[c][3] += w2.w * x;
        }
    }

    // fused finalize: acc[c][i] = dX[n][c][g0+i]; combine with Xn, write out
    int n = nb + a;
    if (n < N) {
        float q = 1.0f + 0.1f * qraw[n];
        const float* xb = Xn + (size_t)n * CSTR;
#pragma unroll
        for (int i = 0; i < 4; i++) {
            float dc[9], xc[9];
#pragma unroll
            for (int c = 0; c < 9; c++) {
                dc[c] = acc[c][i];
                xc[c] = xb[c * 64 + g0 + i];
            }
            float D[3][3], Xm[3][3];
            comp2mat(dc, D);
            comp2mat(xc, Xm);
            float* o = out + ((size_t)n * FDIM + g0 + i) * 9;
#pragma unroll
            for (int r = 0; r < 3; r++)
#pragma unroll
                for (int cc = 0; cc < 3; cc++) {
                    float p = 0.f;
#pragma unroll
                    for (int k = 0; k < 3; k++) p += D[r][k] * D[k][cc];
                    o[r * 3 + cc] = Xm[r][cc] + D[r][cc] + q * p;
                }
        }
    }
}

// ---------------------------------------------------------------- K3: fused edge MLP + message scatter
// (unchanged from Round-13 winner)
#define TE        64
#define ETHR      512
#define WB1_OFF   2048
#define W2PITCH   388
#define A0_OFF    12416
#define A0_PITCH  68
#define A1_OFF    (A0_OFF + 32 * A0_PITCH)
#define A2_OFF    (A1_OFF + 64 * A0_PITCH)
#define R_OFF     A0_OFF
#define CS_OFF    (A2_OFF + 128 * A0_PITCH)
#define BS_OFF    (CS_OFF + 64)
#define RPITCH    200
#define EDGE_SMEM ((BS_OFF + 384) * 4)   // 112384 B -> 2 CTAs/SM

__global__ void __launch_bounds__(ETHR, 2) edge_kernel(
    const float* __restrict__ rfv, const float* __restrict__ dij,
    const int* __restrict__ pairs,
    const float* __restrict__ W0, const float* __restrict__ b0,
    const float* __restrict__ W1, const float* __restrict__ b1,
    const float* __restrict__ W2, const float* __restrict__ b2,
    const float* __restrict__ Y, float* __restrict__ Msg, int E)
{
    extern __shared__ float sm[];
    float* Wb = sm;
    float* A0 = sm + A0_OFF;
    float* A1 = sm + A1_OFF;
    float* A2 = sm + A2_OFF;
    float* Cs = sm + CS_OFF;
    float* Bs = sm + BS_OFF;

    int t  = threadIdx.x;
    int e0 = blockIdx.x * TE;

    if (t < 384) {
        float v = (t < 64) ? b0[t] : ((t < 192) ? b1[t - 64] : b2[t - 192]);
        Bs[t] = v;
    }
    if (t < TE) {
        int ge = e0 + t;
        float d = (ge < E) ? dij[ge] : 2.0f;
        Cs[t] = (d < 1.0f) ? 0.5f * (cospif(d) + 1.0f) : 0.0f;
    }
    for (int idx = t; idx < TE * NRBF; idx += ETHR) {       // rfv -> A0[k][e]
        int e = idx >> 5, k = idx & 31;
        int ge = e0 + e;
        A0[k * A0_PITCH + e] = (ge < E) ? rfv[(size_t)ge * NRBF + k] : 0.f;
    }
    for (int idx = t; idx < 64 * 32; idx += ETHR) {         // W0T
        int j = idx >> 5, k = idx & 31;
        Wb[k * 64 + j] = W0[idx];
    }
    for (int idx = t; idx < 128 * 64; idx += ETHR) {        // W1T (disjoint region)
        int j = idx >> 6, k = idx & 63;
        Wb[WB1_OFF + k * 128 + j] = W1[idx];
    }
    __syncthreads();

    int eg = t & 15;          // edge group: edges 4*eg .. 4*eg+3
    int jg = t >> 4;          // output group 0..31

    // ---- layer 1: 32 -> 64, thread tile 4e x 2j
    {
        float b_0 = Bs[2 * jg], b_1 = Bs[2 * jg + 1];
        float acc0[4], acc1[4];
#pragma unroll
        for (int i = 0; i < 4; i++) { acc0[i] = b_0; acc1[i] = b_1; }
#pragma unroll 8
        for (int k = 0; k < 32; k++) {
            float4 a4 = *(const float4*)&A0[k * A0_PITCH + 4 * eg];
            float2 w  = *(const float2*)&Wb[k * 64 + 2 * jg];
            acc0[0] += w.x * a4.x; acc0[1] += w.x * a4.y; acc0[2] += w.x * a4.z; acc0[3] += w.x * a4.w;
            acc1[0] += w.y * a4.x; acc1[1] += w.y * a4.y; acc1[2] += w.y * a4.z; acc1[3] += w.y * a4.w;
        }
#pragma unroll
        for (int i = 0; i < 4; i++) {
            A1[(2 * jg)     * A0_PITCH + 4 * eg + i] = silu_f(acc0[i]);
            A1[(2 * jg + 1) * A0_PITCH + 4 * eg + i] = silu_f(acc1[i]);
        }
    }
    __syncthreads();

    // ---- layer 2: 64 -> 128, thread tile 4e x 4j
    {
        int j0 = 4 * jg;
        float acc[4][4];
#pragma unroll
        for (int jj = 0; jj < 4; jj++) {
            float b = Bs[64 + j0 + jj];
#pragma unroll
            for (int i = 0; i < 4; i++) acc[jj][i] = b;
        }
#pragma unroll 4
        for (int k = 0; k < 64; k++) {
            float4 a4 = *(const float4*)&A1[k * A0_PITCH + 4 * eg];
            float4 w  = *(const float4*)&Wb[WB1_OFF + k * 128 + j0];
            acc[0][0] += w.x * a4.x; acc[0][1] += w.x * a4.y; acc[0][2] += w.x * a4.z; acc[0][3] += w.x * a4.w;
            acc[1][0] += w.y * a4.x; acc[1][1] += w.y * a4.y; acc[1][2] += w.y * a4.z; acc[1][3] += w.y * a4.w;
            acc[2][0] += w.z * a4.x; acc[2][1] += w.z * a4.y; acc[2][2] += w.z * a4.z; acc[2][3] += w.z * a4.w;
            acc[3][0] += w.w * a4.x; acc[3][1] += w.w * a4.y; acc[3][2] += w.w * a4.z; acc[3][3] += w.w * a4.w;
        }
#pragma unroll
        for (int jj = 0; jj < 4; jj++)
#pragma unroll
            for (int i = 0; i < 4; i++)
                A2[(j0 + jj) * A0_PITCH + 4 * eg + i] = silu_f(acc[jj][i]);
    }
    __syncthreads();   // A2 ready; all Wb (W0T/W1T) reads done

    // ---- layer 3: 128 -> 192, two passes of 96 outputs, thread tile 4e x 3j.
    float accL3[2][3][4];
#pragma unroll
    for (int p = 0; p < 2; p++) {
        for (int idx = t; idx < 32 * 128 * 3; idx += ETHR) {
            int jg2 = idx / 384;
            int rem = idx - jg2 * 384;
            int c   = rem >> 7;
            int k   = rem & 127;
            Wb[jg2 * W2PITCH + k * 3 + c] = W2[(size_t)(96 * p + 3 * jg2 + c) * 128 + k];
        }
        __syncthreads();

#pragma unroll
        for (int jj = 0; jj < 3; jj++) {
            float b = Bs[192 + 96 * p + 3 * jg + jj];
#pragma unroll
            for (int i = 0; i < 4; i++) accL3[p][jj][i] = b;
        }
        const float* wbase = &Wb[jg * W2PITCH];
#pragma unroll 2
        for (int kb = 0; kb < 128; kb += 4) {
            float4 w0 = *(const float4*)&wbase[kb * 3];
            float4 w1 = *(const float4*)&wbase[kb * 3 + 4];
            float4 w2 = *(const float4*)&wbase[kb * 3 + 8];
            float4 a0 = *(const float4*)&A2[(kb + 0) * A0_PITCH + 4 * eg];
            float4 a1 = *(const float4*)&A2[(kb + 1) * A0_PITCH + 4 * eg];
            accL3[p][0][0] += w0.x*a0.x; accL3[p][0][1] += w0.x*a0.y; accL3[p][0][2] += w0.x*a0.z; accL3[p][0][3] += w0.x*a0.w;
            accL3[p][1][0] += w0.y*a0.x; accL3[p][1][1] += w0.y*a0.y; accL3[p][1][2] += w0.y*a0.z; accL3[p][1][3] += w0.y*a0.w;
            accL3[p][2][0] += w0.z*a0.x; accL3[p][2][1] += w0.z*a0.y; accL3[p][2][2] += w0.z*a0.z; accL3[p][2][3] += w0.z*a0.w;
            accL3[p][0][0] += w0.w*a1.x; accL3[p][0][1] += w0.w*a1.y; accL3[p][0][2] += w0.w*a1.z; accL3[p][0][3] += w0.w*a1.w;
            accL3[p][1][0] += w1.x*a1.x; accL3[p][1][1] += w1.x*a1.y; accL3[p][1][2] += w1.x*a1.z; accL3[p][1][3] += w1.x*a1.w;
            accL3[p][2][0] += w1.y*a1.x; accL3[p][2][1] += w1.y*a1.y; accL3[p][2][2] += w1.y*a1.z; accL3[p][2][3] += w1.y*a1.w;
            float4 a2 = *(const float4*)&A2[(kb + 2) * A0_PITCH + 4 * eg];
            float4 a3 = *(const float4*)&A2[(kb + 3) * A0_PITCH + 4 * eg];
            accL3[p][0][0] += w1.z*a2.x; accL3[p][0][1] += w1.z*a2.y; accL3[p][0][2] += w1.z*a2.z; accL3[p][0][3] += w1.z*a2.w;
            accL3[p][1][0] += w1.w*a2.x; accL3[p][1][1] += w1.w*a2.y; accL3[p][1][2] += w1.w*a2.z; accL3[p][1][3] += w1.w*a2.w;
            accL3[p][2][0] += w2.x*a2.x; accL3[p][2][1] += w2.x*a2.y; accL3[p][2][2] += w2.x*a2.z; accL3[p][2][3] += w2.x*a2.w;
            accL3[p][0][0] += w2.y*a3.x; accL3[p][0][1] += w2.y*a3.y; accL3[p][0][2] += w2.y*a3.z; accL3[p][0][3] += w2.y*a3.w;
            accL3[p][1][0] += w2.z*a3.x; accL3[p][1][1] += w2.z*a3.y; accL3[p][1][2] += w2.z*a3.z; accL3[p][1][3] += w2.z*a3.w;
            accL3[p][2][0] += w2.w*a3.x; accL3[p][2][1] += w2.w*a3.y; accL3[p][2][2] += w2.w*a3.z; accL3[p][2][3] += w2.w*a3.w;
        }
        __syncthreads();   // Wb reads (and for p=1, A2 reads) done
    }

    // ---- write R (overlays A region), R[e][j] = silu(h)*C[e]
    {
        float* R = sm + R_OFF;
#pragma unroll
        for (int p = 0; p < 2; p++) {
            int jb = 96 * p + 3 * jg;
#pragma unroll
            for (int jj = 0; jj < 3; jj++)
#pragma unroll
                for (int i = 0; i < 4; i++) {
                    int e = 4 * eg + i;
                    R[e * RPITCH + jb + jj] = silu_f(accL3[p][jj][i]) * Cs[e];
                }
        }
    }
    __syncthreads();

    // ---- scatter: msg_c = r_sel(c) * Y_c[src], atomically added into Msg[dst]
    {
        const float* R = sm + R_OFF;
        int warp = t >> 5, lane = t & 31;
        int sub = lane & 15;
        int half = lane >> 4;
#pragma unroll
        for (int pr = 0; pr < 2; pr++) {
            int el = warp * 4 + pr * 2 + half;
            int ge = e0 + el;
            if (ge < E) {
                int dst = pairs[ge];
                int src = pairs[E + ge];
                const float* yb = Y   + (size_t)src * CSTR;
                float*       mb = Msg + (size_t)dst * CSTR;
                int f0 = sub * 4;
                const float* rr = &R[el * RPITCH + f0 * 3];
                float4 r0 = *(const float4*)&rr[0];
                float4 r1 = *(const float4*)&rr[4];
                float4 r2 = *(const float4*)&rr[8];
                float s0x = r0.x, s0y = r0.w, s0z = r1.z, s0w = r2.y;  // ri = 0
                float s1x = r0.y, s1y = r1.x, s1z = r1.w, s1w = r2.z;  // ri = 1
                float s2x = r0.z, s2y = r1.y, s2z = r2.x, s2w = r2.w;  // ri = 2
#pragma unroll
                for (int c = 0; c < 9; c++) {
                    float4 y4 = *(const float4*)&yb[c * 64 + f0];
                    float4 m;
                    if (c == 0) {
                        m = make_float4(s0x * y4.x, s0y * y4.y, s0z * y4.z, s0w * y4.w);
                    } else if (c < 4) {
                        m = make_float4(s1x * y4.x, s1y * y4.y, s1z * y4.z, s1w * y4.w);
                    } else {
                        m = make_float4(s2x * y4.x, s2y * y4.y, s2z * y4.z, s2w * y4.w);
                    }
                    red_v4(&mb[c * 64 + f0], m);
                }
            }
        }
    }
}

// ---------------------------------------------------------------- host
extern "C" void kernel_launch(void* const* d_in, const int* in_sizes, int n_in,
                              void* d_out, int out_size) {
    const float* X    = (const float*)d_in[0];
    const int*   prs  = (const int*)  d_in[1];
    const float* dij  = (const float*)d_in[2];
    const float* rfv  = (const float*)d_in[3];
    const float* q    = (const float*)d_in[4];
    const float* W0   = (const float*)d_in[5];
    const float* b0   = (const float*)d_in[6];
    const float* W1   = (const float*)d_in[7];
    const float* b1   = (const float*)d_in[8];
    const float* W2   = (const float*)d_in[9];
    const float* b2   = (const float*)d_in[10];
    const float* Wt   = (const float*)d_in[11];

    int N = in_sizes[4];          // atomic_charges length
    int E = in_sizes[2];          // d_ij length

    float *pXn, *pY, *pM;
    cudaGetSymbolAddress((void**)&pXn, g_Xn);
    cudaGetSymbolAddress((void**)&pY,  g_Y);
    cudaGetSymbolAddress((void**)&pM,  g_Mg);

    cudaFuncSetAttribute(edge_kernel, cudaFuncAttributeMaxDynamicSharedMemorySize, EDGE_SMEM);
    cudaFuncSetAttribute(mix1_fused,  cudaFuncAttributeMaxDynamicSharedMemorySize, MIX_SMEM);
    cudaFuncSetAttribute(mix2_fused,  cudaFuncAttributeMaxDynamicSharedMemorySize, MIX_SMEM);

    int mix_blocks = (N + MIX_AB - 1) / MIX_AB;

    mix1_fused<<<mix_blocks, 256, MIX_SMEM>>>(X, pXn, pY, Wt, N);
    zero_kernel<<<2048, 256>>>((float4*)pM, N * (CSTR / 4));
    edge_kernel<<<(E + TE - 1) / TE, ETHR, EDGE_SMEM>>>(rfv, dij, prs,
                                                        W0, b0, W1, b1, W2, b2,
                                                        pY, pM, E);
    mix2_fused<<<mix_blocks, 256, MIX_SMEM>>>(pY, pM, pXn, q, (float*)d_out,
                                              Wt + 3 * 64 * 64, N);
}